// round 8
// baseline (speedup 1.0000x reference)
#include <cuda_runtime.h>

#define NE 64
#define NH 2048
#define NF 1408
#define NM 16

typedef unsigned long long ull;

// SwiGLU intermediate scratch: [E, M, F] fp32 = 5.77 MB (L2-resident)
__device__ float g_inter[(size_t)NE * NM * NF];

__device__ __forceinline__ ull pack2(float lo, float hi) {
    ull r;
    asm("mov.b64 %0, {%1, %2};" : "=l"(r) : "f"(lo), "f"(hi));
    return r;
}
__device__ __forceinline__ void fma2(ull& d, ull a, ull b) {
    asm("fma.rn.f32x2 %0, %1, %2, %0;" : "+l"(d) : "l"(a), "l"(b));
}
__device__ __forceinline__ float2 unpack2(ull v) {
    float2 r;
    asm("mov.b64 {%0, %1}, %2;" : "=f"(r.x), "=f"(r.y) : "l"(v));
    return r;
}

#define XS_PAD 20   // 80B row stride: 16B-aligned for LDS.128

// ---------------------------------------------------------------------------
// Kernel 1: inter = silu(x @ gate) * (x @ up), per expert.
// 128 threads/CTA, 1 F-column/thread, grid (11, 64).
// Weights prefetched in blocks of 8 with double buffering (A/B).
// ---------------------------------------------------------------------------
#define K1_HCHUNK 512
#define K1_NB (K1_HCHUNK / 8)       // 64 blocks
#define K1_NPAIR (K1_NB / 2)        // 32 pairs

__global__ __launch_bounds__(128) void moe_gateup_kernel(
    const float* __restrict__ x,
    const float* __restrict__ gate,
    const float* __restrict__ up)
{
    __shared__ float xs[K1_HCHUNK][XS_PAD];

    const int e = blockIdx.y;
    const int f = blockIdx.x * 128 + threadIdx.x;

    const float* xe = x + (size_t)e * NM * NH;
    const float* gp = gate + (size_t)e * NH * NF + f;
    const float* upp = up + (size_t)e * NH * NF + f;

    ull accg[8], accu[8];
#pragma unroll
    for (int j = 0; j < 8; j++) { accg[j] = 0ull; accu[j] = 0ull; }

    for (int hc = 0; hc < NH; hc += K1_HCHUNK) {
        __syncthreads();
#pragma unroll
        for (int mm = 0; mm < NM; mm++) {
#pragma unroll
            for (int hh = threadIdx.x; hh < K1_HCHUNK; hh += 128)
                xs[hh][mm] = xe[(size_t)mm * NH + hc + hh];
        }
        __syncthreads();

        const float* g0 = gp + (size_t)hc * NF;
        const float* u0 = upp + (size_t)hc * NF;

        float wgA[8], wuA[8], wgB[8], wuB[8];
        // prologue: load block 0
#pragma unroll
        for (int u = 0; u < 8; u++) {
            wgA[u] = __ldg(g0 + (size_t)u * NF);
            wuA[u] = __ldg(u0 + (size_t)u * NF);
        }

        for (int p = 0; p < K1_NPAIR; p++) {
            const int b1 = 2 * p + 1;
            const int b2 = (2 * p + 2 < K1_NB) ? 2 * p + 2 : K1_NB - 1;
            // prefetch block b1 into B
#pragma unroll
            for (int u = 0; u < 8; u++) {
                wgB[u] = __ldg(g0 + (size_t)(b1 * 8 + u) * NF);
                wuB[u] = __ldg(u0 + (size_t)(b1 * 8 + u) * NF);
            }
            // compute block 2p from A
            {
                const int hb = 2 * p * 8;
#pragma unroll
                for (int u = 0; u < 8; u++) {
                    ull bg = pack2(wgA[u], wgA[u]);
                    ull bu = pack2(wuA[u], wuA[u]);
                    const ulonglong2* xr = reinterpret_cast<const ulonglong2*>(&xs[hb + u][0]);
                    ulonglong2 x01 = xr[0], x23 = xr[1], x45 = xr[2], x67 = xr[3];
                    fma2(accg[0], x01.x, bg); fma2(accu[0], x01.x, bu);
                    fma2(accg[1], x01.y, bg); fma2(accu[1], x01.y, bu);
                    fma2(accg[2], x23.x, bg); fma2(accu[2], x23.x, bu);
                    fma2(accg[3], x23.y, bg); fma2(accu[3], x23.y, bu);
                    fma2(accg[4], x45.x, bg); fma2(accu[4], x45.x, bu);
                    fma2(accg[5], x45.y, bg); fma2(accu[5], x45.y, bu);
                    fma2(accg[6], x67.x, bg); fma2(accu[6], x67.x, bu);
                    fma2(accg[7], x67.y, bg); fma2(accu[7], x67.y, bu);
                }
            }
            // prefetch block b2 into A
#pragma unroll
            for (int u = 0; u < 8; u++) {
                wgA[u] = __ldg(g0 + (size_t)(b2 * 8 + u) * NF);
                wuA[u] = __ldg(u0 + (size_t)(b2 * 8 + u) * NF);
            }
            // compute block 2p+1 from B
            {
                const int hb = b1 * 8;
#pragma unroll
                for (int u = 0; u < 8; u++) {
                    ull bg = pack2(wgB[u], wgB[u]);
                    ull bu = pack2(wuB[u], wuB[u]);
                    const ulonglong2* xr = reinterpret_cast<const ulonglong2*>(&xs[hb + u][0]);
                    ulonglong2 x01 = xr[0], x23 = xr[1], x45 = xr[2], x67 = xr[3];
                    fma2(accg[0], x01.x, bg); fma2(accu[0], x01.x, bu);
                    fma2(accg[1], x01.y, bg); fma2(accu[1], x01.y, bu);
                    fma2(accg[2], x23.x, bg); fma2(accu[2], x23.x, bu);
                    fma2(accg[3], x23.y, bg); fma2(accu[3], x23.y, bu);
                    fma2(accg[4], x45.x, bg); fma2(accu[4], x45.x, bu);
                    fma2(accg[5], x45.y, bg); fma2(accu[5], x45.y, bu);
                    fma2(accg[6], x67.x, bg); fma2(accu[6], x67.x, bu);
                    fma2(accg[7], x67.y, bg); fma2(accu[7], x67.y, bu);
                }
            }
        }
    }

    float* ip = g_inter + (size_t)e * NM * NF + f;
#pragma unroll
    for (int j = 0; j < 8; j++) {
        float2 g = unpack2(accg[j]);
        float2 u = unpack2(accu[j]);
        float s0 = g.x / (1.0f + __expf(-g.x)) * u.x;
        float s1 = g.y / (1.0f + __expf(-g.y)) * u.y;
        ip[(size_t)(2 * j) * NF] = s0;
        ip[(size_t)(2 * j + 1) * NF] = s1;
    }
}

// ---------------------------------------------------------------------------
// Kernel 2: out = inter @ down  (down is [E, F, H], h contiguous)
// 128 threads/CTA, 1 H-column/thread, grid (16, 64) = 1024 CTAs.
// ---------------------------------------------------------------------------
#define K2_FCHUNK 352
#define K2_NB (K2_FCHUNK / 8)       // 44
#define K2_NPAIR (K2_NB / 2)        // 22

__global__ __launch_bounds__(128) void moe_down_kernel(
    const float* __restrict__ down,
    float* __restrict__ out)
{
    __shared__ float xs[K2_FCHUNK][XS_PAD];

    const int e = blockIdx.y;
    const int h0 = blockIdx.x * 128 + threadIdx.x;

    const float* ie = g_inter + (size_t)e * NM * NF;
    const float* dp = down + (size_t)e * NF * NH + h0;

    ull acc[8];
#pragma unroll
    for (int j = 0; j < 8; j++) acc[j] = 0ull;

    for (int fc = 0; fc < NF; fc += K2_FCHUNK) {
        __syncthreads();
#pragma unroll
        for (int mm = 0; mm < NM; mm++) {
            for (int hh = threadIdx.x; hh < K2_FCHUNK; hh += 128)
                xs[hh][mm] = ie[(size_t)mm * NF + fc + hh];
        }
        __syncthreads();

        const float* d0 = dp + (size_t)fc * NH;

        float wA[8], wB[8];
#pragma unroll
        for (int u = 0; u < 8; u++) wA[u] = __ldg(d0 + (size_t)u * NH);

        for (int p = 0; p < K2_NPAIR; p++) {
            const int b1 = 2 * p + 1;
            const int b2 = (2 * p + 2 < K2_NB) ? 2 * p + 2 : K2_NB - 1;
#pragma unroll
            for (int u = 0; u < 8; u++)
                wB[u] = __ldg(d0 + (size_t)(b1 * 8 + u) * NH);
            {
                const int hb = 2 * p * 8;
#pragma unroll
                for (int u = 0; u < 8; u++) {
                    ull b = pack2(wA[u], wA[u]);
                    const ulonglong2* xr = reinterpret_cast<const ulonglong2*>(&xs[hb + u][0]);
                    ulonglong2 x01 = xr[0], x23 = xr[1], x45 = xr[2], x67 = xr[3];
                    fma2(acc[0], x01.x, b); fma2(acc[1], x01.y, b);
                    fma2(acc[2], x23.x, b); fma2(acc[3], x23.y, b);
                    fma2(acc[4], x45.x, b); fma2(acc[5], x45.y, b);
                    fma2(acc[6], x67.x, b); fma2(acc[7], x67.y, b);
                }
            }
#pragma unroll
            for (int u = 0; u < 8; u++)
                wA[u] = __ldg(d0 + (size_t)(b2 * 8 + u) * NH);
            {
                const int hb = b1 * 8;
#pragma unroll
                for (int u = 0; u < 8; u++) {
                    ull b = pack2(wB[u], wB[u]);
                    const ulonglong2* xr = reinterpret_cast<const ulonglong2*>(&xs[hb + u][0]);
                    ulonglong2 x01 = xr[0], x23 = xr[1], x45 = xr[2], x67 = xr[3];
                    fma2(acc[0], x01.x, b); fma2(acc[1], x01.y, b);
                    fma2(acc[2], x23.x, b); fma2(acc[3], x23.y, b);
                    fma2(acc[4], x45.x, b); fma2(acc[5], x45.y, b);
                    fma2(acc[6], x67.x, b); fma2(acc[7], x67.y, b);
                }
            }
        }
    }

    float* op = out + (size_t)e * NM * NH + h0;
#pragma unroll
    for (int j = 0; j < 8; j++) {
        float2 r = unpack2(acc[j]);
        op[(size_t)(2 * j) * NH]     = r.x;
        op[(size_t)(2 * j + 1) * NH] = r.y;
    }
}

extern "C" void kernel_launch(void* const* d_in, const int* in_sizes, int n_in,
                              void* d_out, int out_size)
{
    const float* x    = (const float*)d_in[0];  // [T=1024, H=2048]
    const float* gate = (const float*)d_in[1];  // [E, H, F]
    const float* up   = (const float*)d_in[2];  // [E, H, F]
    const float* down = (const float*)d_in[3];  // [E, F, H]
    float* out = (float*)d_out;                 // [T, H] fp32

    dim3 g1(NF / 128, NE);   // 11 x 64 = 704 CTAs
    moe_gateup_kernel<<<g1, 128>>>(x, gate, up);

    dim3 g2(NH / 128, NE);   // 16 x 64 = 1024 CTAs
    moe_down_kernel<<<g2, 128>>>(down, out);
}

// round 9
// speedup vs baseline: 1.2275x; 1.2275x over previous
#include <cuda_runtime.h>

#define NE 64
#define NH 2048
#define NF 1408
#define NM 16

typedef unsigned long long ull;

// SwiGLU intermediate scratch: [E, M, F] fp32 = 5.77 MB
__device__ float g_inter[(size_t)NE * NM * NF];
// down-proj partial sums: [2, E, M, H] fp32 = 16.8 MB
__device__ float g_part[(size_t)2 * NE * NM * NH];

__device__ __forceinline__ ull pack2(float lo, float hi) {
    ull r;
    asm("mov.b64 %0, {%1, %2};" : "=l"(r) : "f"(lo), "f"(hi));
    return r;
}
__device__ __forceinline__ void fma2(ull& d, ull a, ull b) {
    asm("fma.rn.f32x2 %0, %1, %2, %0;" : "+l"(d) : "l"(a), "l"(b));
}
__device__ __forceinline__ float2 unpack2(ull v) {
    float2 r;
    asm("mov.b64 {%0, %1}, %2;" : "=f"(r.x), "=f"(r.y) : "l"(v));
    return r;
}

#define XS_PAD 20   // 80B row stride, 16B-aligned for LDS.128

// ---------------------------------------------------------------------------
// Kernel 1: inter = silu(x@gate) * (x@up).  64 thr/CTA, 2 f-cols/thread
// (R = 2 cols x 2 mats = 4 weights per x-read).  grid (11, 64).
// ---------------------------------------------------------------------------
#define K1_CHUNK 256
#define K1_NB (K1_CHUNK / 4)    // 64 blocks of 4 h-steps
#define K1_NP (K1_NB / 2)       // 32 pairs

__global__ __launch_bounds__(64) void moe_gateup_kernel(
    const float* __restrict__ x,
    const float* __restrict__ gate,
    const float* __restrict__ up)
{
    __shared__ float xs[K1_CHUNK][XS_PAD];

    const int e = blockIdx.y;
    const int f = blockIdx.x * 128 + threadIdx.x * 2;

    const float* xe = x + (size_t)e * NM * NH;
    const float* gp = gate + (size_t)e * NH * NF + f;
    const float* upp = up + (size_t)e * NH * NF + f;

    ull accg[2][8], accu[2][8];
#pragma unroll
    for (int c = 0; c < 2; c++)
#pragma unroll
        for (int j = 0; j < 8; j++) { accg[c][j] = 0ull; accu[c][j] = 0ull; }

    for (int hc = 0; hc < NH; hc += K1_CHUNK) {
        __syncthreads();
#pragma unroll
        for (int mm = 0; mm < NM; mm++) {
#pragma unroll
            for (int hh = threadIdx.x; hh < K1_CHUNK; hh += 64)
                xs[hh][mm] = xe[(size_t)mm * NH + hc + hh];
        }
        __syncthreads();

        const float* g0 = gp + (size_t)hc * NF;
        const float* u0 = upp + (size_t)hc * NF;

        float2 gA[4], uA[4], gB[4], uB[4];
#pragma unroll
        for (int s = 0; s < 4; s++) {
            gA[s] = __ldg((const float2*)(g0 + (size_t)s * NF));
            uA[s] = __ldg((const float2*)(u0 + (size_t)s * NF));
        }

        for (int p = 0; p < K1_NP; p++) {
            const int b1 = 2 * p + 1;
            const int b2 = (2 * p + 2 < K1_NB) ? 2 * p + 2 : K1_NB - 1;
#pragma unroll
            for (int s = 0; s < 4; s++) {
                gB[s] = __ldg((const float2*)(g0 + (size_t)(b1 * 4 + s) * NF));
                uB[s] = __ldg((const float2*)(u0 + (size_t)(b1 * 4 + s) * NF));
            }
            {
                const int hb = 2 * p * 4;
#pragma unroll
                for (int s = 0; s < 4; s++) {
                    ull bg0 = pack2(gA[s].x, gA[s].x), bg1 = pack2(gA[s].y, gA[s].y);
                    ull bu0 = pack2(uA[s].x, uA[s].x), bu1 = pack2(uA[s].y, uA[s].y);
                    const ulonglong2* xr = reinterpret_cast<const ulonglong2*>(&xs[hb + s][0]);
                    ulonglong2 x01 = xr[0], x23 = xr[1], x45 = xr[2], x67 = xr[3];
                    fma2(accg[0][0], x01.x, bg0); fma2(accg[1][0], x01.x, bg1);
                    fma2(accu[0][0], x01.x, bu0); fma2(accu[1][0], x01.x, bu1);
                    fma2(accg[0][1], x01.y, bg0); fma2(accg[1][1], x01.y, bg1);
                    fma2(accu[0][1], x01.y, bu0); fma2(accu[1][1], x01.y, bu1);
                    fma2(accg[0][2], x23.x, bg0); fma2(accg[1][2], x23.x, bg1);
                    fma2(accu[0][2], x23.x, bu0); fma2(accu[1][2], x23.x, bu1);
                    fma2(accg[0][3], x23.y, bg0); fma2(accg[1][3], x23.y, bg1);
                    fma2(accu[0][3], x23.y, bu0); fma2(accu[1][3], x23.y, bu1);
                    fma2(accg[0][4], x45.x, bg0); fma2(accg[1][4], x45.x, bg1);
                    fma2(accu[0][4], x45.x, bu0); fma2(accu[1][4], x45.x, bu1);
                    fma2(accg[0][5], x45.y, bg0); fma2(accg[1][5], x45.y, bg1);
                    fma2(accu[0][5], x45.y, bu0); fma2(accu[1][5], x45.y, bu1);
                    fma2(accg[0][6], x67.x, bg0); fma2(accg[1][6], x67.x, bg1);
                    fma2(accu[0][6], x67.x, bu0); fma2(accu[1][6], x67.x, bu1);
                    fma2(accg[0][7], x67.y, bg0); fma2(accg[1][7], x67.y, bg1);
                    fma2(accu[0][7], x67.y, bu0); fma2(accu[1][7], x67.y, bu1);
                }
            }
#pragma unroll
            for (int s = 0; s < 4; s++) {
                gA[s] = __ldg((const float2*)(g0 + (size_t)(b2 * 4 + s) * NF));
                uA[s] = __ldg((const float2*)(u0 + (size_t)(b2 * 4 + s) * NF));
            }
            {
                const int hb = b1 * 4;
#pragma unroll
                for (int s = 0; s < 4; s++) {
                    ull bg0 = pack2(gB[s].x, gB[s].x), bg1 = pack2(gB[s].y, gB[s].y);
                    ull bu0 = pack2(uB[s].x, uB[s].x), bu1 = pack2(uB[s].y, uB[s].y);
                    const ulonglong2* xr = reinterpret_cast<const ulonglong2*>(&xs[hb + s][0]);
                    ulonglong2 x01 = xr[0], x23 = xr[1], x45 = xr[2], x67 = xr[3];
                    fma2(accg[0][0], x01.x, bg0); fma2(accg[1][0], x01.x, bg1);
                    fma2(accu[0][0], x01.x, bu0); fma2(accu[1][0], x01.x, bu1);
                    fma2(accg[0][1], x01.y, bg0); fma2(accg[1][1], x01.y, bg1);
                    fma2(accu[0][1], x01.y, bu0); fma2(accu[1][1], x01.y, bu1);
                    fma2(accg[0][2], x23.x, bg0); fma2(accg[1][2], x23.x, bg1);
                    fma2(accu[0][2], x23.x, bu0); fma2(accu[1][2], x23.x, bu1);
                    fma2(accg[0][3], x23.y, bg0); fma2(accg[1][3], x23.y, bg1);
                    fma2(accu[0][3], x23.y, bu0); fma2(accu[1][3], x23.y, bu1);
                    fma2(accg[0][4], x45.x, bg0); fma2(accg[1][4], x45.x, bg1);
                    fma2(accu[0][4], x45.x, bu0); fma2(accu[1][4], x45.x, bu1);
                    fma2(accg[0][5], x45.y, bg0); fma2(accg[1][5], x45.y, bg1);
                    fma2(accu[0][5], x45.y, bu0); fma2(accu[1][5], x45.y, bu1);
                    fma2(accg[0][6], x67.x, bg0); fma2(accg[1][6], x67.x, bg1);
                    fma2(accu[0][6], x67.x, bu0); fma2(accu[1][6], x67.x, bu1);
                    fma2(accg[0][7], x67.y, bg0); fma2(accg[1][7], x67.y, bg1);
                    fma2(accu[0][7], x67.y, bu0); fma2(accu[1][7], x67.y, bu1);
                }
            }
        }
    }

    float* ip = g_inter + (size_t)e * NM * NF + f;
#pragma unroll
    for (int j = 0; j < 8; j++) {
        float2 g0v = unpack2(accg[0][j]), g1v = unpack2(accg[1][j]);
        float2 u0v = unpack2(accu[0][j]), u1v = unpack2(accu[1][j]);
        float2 o_m0, o_m1;
        o_m0.x = g0v.x / (1.0f + __expf(-g0v.x)) * u0v.x;
        o_m0.y = g1v.x / (1.0f + __expf(-g1v.x)) * u1v.x;
        o_m1.x = g0v.y / (1.0f + __expf(-g0v.y)) * u0v.y;
        o_m1.y = g1v.y / (1.0f + __expf(-g1v.y)) * u1v.y;
        *reinterpret_cast<float2*>(ip + (size_t)(2 * j) * NF)     = o_m0;
        *reinterpret_cast<float2*>(ip + (size_t)(2 * j + 1) * NF) = o_m1;
    }
}

// ---------------------------------------------------------------------------
// Kernel 2: partial down-proj.  64 thr/CTA, 4 h-cols/thread (R=4),
// F-split 2 over blockIdx.z, partials to g_part.  grid (8, 64, 2).
// ---------------------------------------------------------------------------
#define K2_CHUNK 352
#define K2_FSPLIT 704
#define K2_NB (K2_CHUNK / 4)    // 88
#define K2_NP (K2_NB / 2)       // 44

__global__ __launch_bounds__(64) void moe_down_kernel(
    const float* __restrict__ down)
{
    __shared__ float xs[K2_CHUNK][XS_PAD];

    const int e = blockIdx.y;
    const int z = blockIdx.z;
    const int h0 = blockIdx.x * 256 + threadIdx.x * 4;

    const float* ie = g_inter + (size_t)e * NM * NF + (size_t)z * K2_FSPLIT;
    const float* dp = down + (size_t)e * NF * NH + (size_t)z * K2_FSPLIT * NH + h0;

    ull acc[4][8];
#pragma unroll
    for (int c = 0; c < 4; c++)
#pragma unroll
        for (int j = 0; j < 8; j++) acc[c][j] = 0ull;

    for (int fc = 0; fc < K2_FSPLIT; fc += K2_CHUNK) {
        __syncthreads();
#pragma unroll
        for (int mm = 0; mm < NM; mm++) {
            for (int hh = threadIdx.x; hh < K2_CHUNK; hh += 64)
                xs[hh][mm] = ie[(size_t)mm * NF + fc + hh];
        }
        __syncthreads();

        const float* d0 = dp + (size_t)fc * NH;

        float4 wA[4], wB[4];
#pragma unroll
        for (int s = 0; s < 4; s++)
            wA[s] = __ldg((const float4*)(d0 + (size_t)s * NH));

        for (int p = 0; p < K2_NP; p++) {
            const int b1 = 2 * p + 1;
            const int b2 = (2 * p + 2 < K2_NB) ? 2 * p + 2 : K2_NB - 1;
#pragma unroll
            for (int s = 0; s < 4; s++)
                wB[s] = __ldg((const float4*)(d0 + (size_t)(b1 * 4 + s) * NH));
            {
                const int hb = 2 * p * 4;
#pragma unroll
                for (int s = 0; s < 4; s++) {
                    ull b0 = pack2(wA[s].x, wA[s].x), b1w = pack2(wA[s].y, wA[s].y);
                    ull b2w = pack2(wA[s].z, wA[s].z), b3 = pack2(wA[s].w, wA[s].w);
                    const ulonglong2* xr = reinterpret_cast<const ulonglong2*>(&xs[hb + s][0]);
                    ulonglong2 x01 = xr[0], x23 = xr[1], x45 = xr[2], x67 = xr[3];
                    fma2(acc[0][0], x01.x, b0); fma2(acc[1][0], x01.x, b1w);
                    fma2(acc[2][0], x01.x, b2w); fma2(acc[3][0], x01.x, b3);
                    fma2(acc[0][1], x01.y, b0); fma2(acc[1][1], x01.y, b1w);
                    fma2(acc[2][1], x01.y, b2w); fma2(acc[3][1], x01.y, b3);
                    fma2(acc[0][2], x23.x, b0); fma2(acc[1][2], x23.x, b1w);
                    fma2(acc[2][2], x23.x, b2w); fma2(acc[3][2], x23.x, b3);
                    fma2(acc[0][3], x23.y, b0); fma2(acc[1][3], x23.y, b1w);
                    fma2(acc[2][3], x23.y, b2w); fma2(acc[3][3], x23.y, b3);
                    fma2(acc[0][4], x45.x, b0); fma2(acc[1][4], x45.x, b1w);
                    fma2(acc[2][4], x45.x, b2w); fma2(acc[3][4], x45.x, b3);
                    fma2(acc[0][5], x45.y, b0); fma2(acc[1][5], x45.y, b1w);
                    fma2(acc[2][5], x45.y, b2w); fma2(acc[3][5], x45.y, b3);
                    fma2(acc[0][6], x67.x, b0); fma2(acc[1][6], x67.x, b1w);
                    fma2(acc[2][6], x67.x, b2w); fma2(acc[3][6], x67.x, b3);
                    fma2(acc[0][7], x67.y, b0); fma2(acc[1][7], x67.y, b1w);
                    fma2(acc[2][7], x67.y, b2w); fma2(acc[3][7], x67.y, b3);
                }
            }
#pragma unroll
            for (int s = 0; s < 4; s++)
                wA[s] = __ldg((const float4*)(d0 + (size_t)(b2 * 4 + s) * NH));
            {
                const int hb = b1 * 4;
#pragma unroll
                for (int s = 0; s < 4; s++) {
                    ull b0 = pack2(wB[s].x, wB[s].x), b1w = pack2(wB[s].y, wB[s].y);
                    ull b2w = pack2(wB[s].z, wB[s].z), b3 = pack2(wB[s].w, wB[s].w);
                    const ulonglong2* xr = reinterpret_cast<const ulonglong2*>(&xs[hb + s][0]);
                    ulonglong2 x01 = xr[0], x23 = xr[1], x45 = xr[2], x67 = xr[3];
                    fma2(acc[0][0], x01.x, b0); fma2(acc[1][0], x01.x, b1w);
                    fma2(acc[2][0], x01.x, b2w); fma2(acc[3][0], x01.x, b3);
                    fma2(acc[0][1], x01.y, b0); fma2(acc[1][1], x01.y, b1w);
                    fma2(acc[2][1], x01.y, b2w); fma2(acc[3][1], x01.y, b3);
                    fma2(acc[0][2], x23.x, b0); fma2(acc[1][2], x23.x, b1w);
                    fma2(acc[2][2], x23.x, b2w); fma2(acc[3][2], x23.x, b3);
                    fma2(acc[0][3], x23.y, b0); fma2(acc[1][3], x23.y, b1w);
                    fma2(acc[2][3], x23.y, b2w); fma2(acc[3][3], x23.y, b3);
                    fma2(acc[0][4], x45.x, b0); fma2(acc[1][4], x45.x, b1w);
                    fma2(acc[2][4], x45.x, b2w); fma2(acc[3][4], x45.x, b3);
                    fma2(acc[0][5], x45.y, b0); fma2(acc[1][5], x45.y, b1w);
                    fma2(acc[2][5], x45.y, b2w); fma2(acc[3][5], x45.y, b3);
                    fma2(acc[0][6], x67.x, b0); fma2(acc[1][6], x67.x, b1w);
                    fma2(acc[2][6], x67.x, b2w); fma2(acc[3][6], x67.x, b3);
                    fma2(acc[0][7], x67.y, b0); fma2(acc[1][7], x67.y, b1w);
                    fma2(acc[2][7], x67.y, b2w); fma2(acc[3][7], x67.y, b3);
                }
            }
        }
    }

    float* pp = g_part + ((size_t)z * NE * NM + (size_t)e * NM) * NH + h0;
#pragma unroll
    for (int j = 0; j < 8; j++) {
        float2 r0 = unpack2(acc[0][j]), r1 = unpack2(acc[1][j]);
        float2 r2 = unpack2(acc[2][j]), r3 = unpack2(acc[3][j]);
        float4 v0 = make_float4(r0.x, r1.x, r2.x, r3.x);
        float4 v1 = make_float4(r0.y, r1.y, r2.y, r3.y);
        *reinterpret_cast<float4*>(pp + (size_t)(2 * j) * NH)     = v0;
        *reinterpret_cast<float4*>(pp + (size_t)(2 * j + 1) * NH) = v1;
    }
}

// ---------------------------------------------------------------------------
// Kernel 3: out = part[0] + part[1]
// ---------------------------------------------------------------------------
__global__ __launch_bounds__(256) void moe_reduce_kernel(float* __restrict__ out)
{
    const size_t i = (size_t)blockIdx.x * 256 + threadIdx.x;   // float4 index
    const size_t n4 = (size_t)NE * NM * NH / 4;
    if (i < n4) {
        const float4* p0 = reinterpret_cast<const float4*>(g_part);
        const float4* p1 = reinterpret_cast<const float4*>(g_part + (size_t)NE * NM * NH);
        float4 a = p0[i], b = p1[i];
        float4 r = make_float4(a.x + b.x, a.y + b.y, a.z + b.z, a.w + b.w);
        reinterpret_cast<float4*>(out)[i] = r;
    }
}

extern "C" void kernel_launch(void* const* d_in, const int* in_sizes, int n_in,
                              void* d_out, int out_size)
{
    const float* x    = (const float*)d_in[0];  // [T=1024, H=2048]
    const float* gate = (const float*)d_in[1];  // [E, H, F]
    const float* up   = (const float*)d_in[2];  // [E, H, F]
    const float* down = (const float*)d_in[3];  // [E, F, H]
    float* out = (float*)d_out;                 // [T, H] fp32

    dim3 g1(NF / 128, NE);        // 11 x 64 = 704 CTAs, 64 thr
    moe_gateup_kernel<<<g1, 64>>>(x, gate, up);

    dim3 g2(NH / 256, NE, 2);     // 8 x 64 x 2 = 1024 CTAs, 64 thr
    moe_down_kernel<<<g2, 64>>>(down);

    const int n4 = NE * NM * NH / 4;              // 524288
    moe_reduce_kernel<<<(n4 + 255) / 256, 256>>>(out);
}

// round 10
// speedup vs baseline: 1.2368x; 1.0076x over previous
#include <cuda_runtime.h>

#define NE 64
#define NH 2048
#define NF 1408
#define NM 16

typedef unsigned long long ull;

// SwiGLU intermediate scratch: [E, M, F] fp32 = 5.77 MB
__device__ float g_inter[(size_t)NE * NM * NF];
// down-proj partial sums: [2, E, M, H] fp32 = 16.8 MB
__device__ float g_part[(size_t)2 * NE * NM * NH];

__device__ __forceinline__ ull pack2(float lo, float hi) {
    ull r;
    asm("mov.b64 %0, {%1, %2};" : "=l"(r) : "f"(lo), "f"(hi));
    return r;
}
__device__ __forceinline__ void fma2(ull& d, ull a, ull b) {
    asm("fma.rn.f32x2 %0, %1, %2, %0;" : "+l"(d) : "l"(a), "l"(b));
}
__device__ __forceinline__ float2 unpack2(ull v) {
    float2 r;
    asm("mov.b64 {%0, %1}, %2;" : "=f"(r.x), "=f"(r.y) : "l"(v));
    return r;
}

#define XS_PAD 20   // 80B row stride, 16B-aligned for LDS.128

// ---------------------------------------------------------------------------
// Kernel 1: inter = silu(x@gate) * (x@up).  64 thr/CTA, 2 f-cols/thread
// (R = 2 cols x 2 mats = 4 weights per x-read).  grid (11, 64).
// ---------------------------------------------------------------------------
#define K1_CHUNK 256
#define K1_NB (K1_CHUNK / 4)    // 64 blocks of 4 h-steps
#define K1_NP (K1_NB / 2)       // 32 pairs

__global__ __launch_bounds__(64) void moe_gateup_kernel(
    const float* __restrict__ x,
    const float* __restrict__ gate,
    const float* __restrict__ up)
{
    __shared__ float xs[K1_CHUNK][XS_PAD];

    const int e = blockIdx.y;
    const int f = blockIdx.x * 128 + threadIdx.x * 2;

    const float* xe = x + (size_t)e * NM * NH;
    const float* gp = gate + (size_t)e * NH * NF + f;
    const float* upp = up + (size_t)e * NH * NF + f;

    ull accg[2][8], accu[2][8];
#pragma unroll
    for (int c = 0; c < 2; c++)
#pragma unroll
        for (int j = 0; j < 8; j++) { accg[c][j] = 0ull; accu[c][j] = 0ull; }

    for (int hc = 0; hc < NH; hc += K1_CHUNK) {
        __syncthreads();
#pragma unroll
        for (int mm = 0; mm < NM; mm++) {
#pragma unroll
            for (int hh = threadIdx.x; hh < K1_CHUNK; hh += 64)
                xs[hh][mm] = xe[(size_t)mm * NH + hc + hh];
        }
        __syncthreads();

        const float* g0 = gp + (size_t)hc * NF;
        const float* u0 = upp + (size_t)hc * NF;

        float2 gA[4], uA[4], gB[4], uB[4];
#pragma unroll
        for (int s = 0; s < 4; s++) {
            gA[s] = __ldg((const float2*)(g0 + (size_t)s * NF));
            uA[s] = __ldg((const float2*)(u0 + (size_t)s * NF));
        }

        for (int p = 0; p < K1_NP; p++) {
            const int b1 = 2 * p + 1;
            const int b2 = (2 * p + 2 < K1_NB) ? 2 * p + 2 : K1_NB - 1;
#pragma unroll
            for (int s = 0; s < 4; s++) {
                gB[s] = __ldg((const float2*)(g0 + (size_t)(b1 * 4 + s) * NF));
                uB[s] = __ldg((const float2*)(u0 + (size_t)(b1 * 4 + s) * NF));
            }
            {
                const int hb = 2 * p * 4;
#pragma unroll
                for (int s = 0; s < 4; s++) {
                    ull bg0 = pack2(gA[s].x, gA[s].x), bg1 = pack2(gA[s].y, gA[s].y);
                    ull bu0 = pack2(uA[s].x, uA[s].x), bu1 = pack2(uA[s].y, uA[s].y);
                    const ulonglong2* xr = reinterpret_cast<const ulonglong2*>(&xs[hb + s][0]);
                    ulonglong2 x01 = xr[0], x23 = xr[1], x45 = xr[2], x67 = xr[3];
                    fma2(accg[0][0], x01.x, bg0); fma2(accg[1][0], x01.x, bg1);
                    fma2(accu[0][0], x01.x, bu0); fma2(accu[1][0], x01.x, bu1);
                    fma2(accg[0][1], x01.y, bg0); fma2(accg[1][1], x01.y, bg1);
                    fma2(accu[0][1], x01.y, bu0); fma2(accu[1][1], x01.y, bu1);
                    fma2(accg[0][2], x23.x, bg0); fma2(accg[1][2], x23.x, bg1);
                    fma2(accu[0][2], x23.x, bu0); fma2(accu[1][2], x23.x, bu1);
                    fma2(accg[0][3], x23.y, bg0); fma2(accg[1][3], x23.y, bg1);
                    fma2(accu[0][3], x23.y, bu0); fma2(accu[1][3], x23.y, bu1);
                    fma2(accg[0][4], x45.x, bg0); fma2(accg[1][4], x45.x, bg1);
                    fma2(accu[0][4], x45.x, bu0); fma2(accu[1][4], x45.x, bu1);
                    fma2(accg[0][5], x45.y, bg0); fma2(accg[1][5], x45.y, bg1);
                    fma2(accu[0][5], x45.y, bu0); fma2(accu[1][5], x45.y, bu1);
                    fma2(accg[0][6], x67.x, bg0); fma2(accg[1][6], x67.x, bg1);
                    fma2(accu[0][6], x67.x, bu0); fma2(accu[1][6], x67.x, bu1);
                    fma2(accg[0][7], x67.y, bg0); fma2(accg[1][7], x67.y, bg1);
                    fma2(accu[0][7], x67.y, bu0); fma2(accu[1][7], x67.y, bu1);
                }
            }
#pragma unroll
            for (int s = 0; s < 4; s++) {
                gA[s] = __ldg((const float2*)(g0 + (size_t)(b2 * 4 + s) * NF));
                uA[s] = __ldg((const float2*)(u0 + (size_t)(b2 * 4 + s) * NF));
            }
            {
                const int hb = b1 * 4;
#pragma unroll
                for (int s = 0; s < 4; s++) {
                    ull bg0 = pack2(gB[s].x, gB[s].x), bg1 = pack2(gB[s].y, gB[s].y);
                    ull bu0 = pack2(uB[s].x, uB[s].x), bu1 = pack2(uB[s].y, uB[s].y);
                    const ulonglong2* xr = reinterpret_cast<const ulonglong2*>(&xs[hb + s][0]);
                    ulonglong2 x01 = xr[0], x23 = xr[1], x45 = xr[2], x67 = xr[3];
                    fma2(accg[0][0], x01.x, bg0); fma2(accg[1][0], x01.x, bg1);
                    fma2(accu[0][0], x01.x, bu0); fma2(accu[1][0], x01.x, bu1);
                    fma2(accg[0][1], x01.y, bg0); fma2(accg[1][1], x01.y, bg1);
                    fma2(accu[0][1], x01.y, bu0); fma2(accu[1][1], x01.y, bu1);
                    fma2(accg[0][2], x23.x, bg0); fma2(accg[1][2], x23.x, bg1);
                    fma2(accu[0][2], x23.x, bu0); fma2(accu[1][2], x23.x, bu1);
                    fma2(accg[0][3], x23.y, bg0); fma2(accg[1][3], x23.y, bg1);
                    fma2(accu[0][3], x23.y, bu0); fma2(accu[1][3], x23.y, bu1);
                    fma2(accg[0][4], x45.x, bg0); fma2(accg[1][4], x45.x, bg1);
                    fma2(accu[0][4], x45.x, bu0); fma2(accu[1][4], x45.x, bu1);
                    fma2(accg[0][5], x45.y, bg0); fma2(accg[1][5], x45.y, bg1);
                    fma2(accu[0][5], x45.y, bu0); fma2(accu[1][5], x45.y, bu1);
                    fma2(accg[0][6], x67.x, bg0); fma2(accg[1][6], x67.x, bg1);
                    fma2(accu[0][6], x67.x, bu0); fma2(accu[1][6], x67.x, bu1);
                    fma2(accg[0][7], x67.y, bg0); fma2(accg[1][7], x67.y, bg1);
                    fma2(accu[0][7], x67.y, bu0); fma2(accu[1][7], x67.y, bu1);
                }
            }
        }
    }

    float* ip = g_inter + (size_t)e * NM * NF + f;
#pragma unroll
    for (int j = 0; j < 8; j++) {
        float2 g0v = unpack2(accg[0][j]), g1v = unpack2(accg[1][j]);
        float2 u0v = unpack2(accu[0][j]), u1v = unpack2(accu[1][j]);
        float2 o_m0, o_m1;
        o_m0.x = g0v.x / (1.0f + __expf(-g0v.x)) * u0v.x;
        o_m0.y = g1v.x / (1.0f + __expf(-g1v.x)) * u1v.x;
        o_m1.x = g0v.y / (1.0f + __expf(-g0v.y)) * u0v.y;
        o_m1.y = g1v.y / (1.0f + __expf(-g1v.y)) * u1v.y;
        *reinterpret_cast<float2*>(ip + (size_t)(2 * j) * NF)     = o_m0;
        *reinterpret_cast<float2*>(ip + (size_t)(2 * j + 1) * NF) = o_m1;
    }
}

// ---------------------------------------------------------------------------
// Kernel 2: partial down-proj.  64 thr/CTA, 4 h-cols/thread (R=4),
// F-split 2 over blockIdx.z, partials to g_part.  grid (8, 64, 2).
// ---------------------------------------------------------------------------
#define K2_CHUNK 352
#define K2_FSPLIT 704
#define K2_NB (K2_CHUNK / 4)    // 88
#define K2_NP (K2_NB / 2)       // 44

__global__ __launch_bounds__(64) void moe_down_kernel(
    const float* __restrict__ down)
{
    __shared__ float xs[K2_CHUNK][XS_PAD];

    const int e = blockIdx.y;
    const int z = blockIdx.z;
    const int h0 = blockIdx.x * 256 + threadIdx.x * 4;

    const float* ie = g_inter + (size_t)e * NM * NF + (size_t)z * K2_FSPLIT;
    const float* dp = down + (size_t)e * NF * NH + (size_t)z * K2_FSPLIT * NH + h0;

    ull acc[4][8];
#pragma unroll
    for (int c = 0; c < 4; c++)
#pragma unroll
        for (int j = 0; j < 8; j++) acc[c][j] = 0ull;

    for (int fc = 0; fc < K2_FSPLIT; fc += K2_CHUNK) {
        __syncthreads();
#pragma unroll
        for (int mm = 0; mm < NM; mm++) {
            for (int hh = threadIdx.x; hh < K2_CHUNK; hh += 64)
                xs[hh][mm] = ie[(size_t)mm * NF + fc + hh];
        }
        __syncthreads();

        const float* d0 = dp + (size_t)fc * NH;

        float4 wA[4], wB[4];
#pragma unroll
        for (int s = 0; s < 4; s++)
            wA[s] = __ldg((const float4*)(d0 + (size_t)s * NH));

        for (int p = 0; p < K2_NP; p++) {
            const int b1 = 2 * p + 1;
            const int b2 = (2 * p + 2 < K2_NB) ? 2 * p + 2 : K2_NB - 1;
#pragma unroll
            for (int s = 0; s < 4; s++)
                wB[s] = __ldg((const float4*)(d0 + (size_t)(b1 * 4 + s) * NH));
            {
                const int hb = 2 * p * 4;
#pragma unroll
                for (int s = 0; s < 4; s++) {
                    ull b0 = pack2(wA[s].x, wA[s].x), b1w = pack2(wA[s].y, wA[s].y);
                    ull b2w = pack2(wA[s].z, wA[s].z), b3 = pack2(wA[s].w, wA[s].w);
                    const ulonglong2* xr = reinterpret_cast<const ulonglong2*>(&xs[hb + s][0]);
                    ulonglong2 x01 = xr[0], x23 = xr[1], x45 = xr[2], x67 = xr[3];
                    fma2(acc[0][0], x01.x, b0); fma2(acc[1][0], x01.x, b1w);
                    fma2(acc[2][0], x01.x, b2w); fma2(acc[3][0], x01.x, b3);
                    fma2(acc[0][1], x01.y, b0); fma2(acc[1][1], x01.y, b1w);
                    fma2(acc[2][1], x01.y, b2w); fma2(acc[3][1], x01.y, b3);
                    fma2(acc[0][2], x23.x, b0); fma2(acc[1][2], x23.x, b1w);
                    fma2(acc[2][2], x23.x, b2w); fma2(acc[3][2], x23.x, b3);
                    fma2(acc[0][3], x23.y, b0); fma2(acc[1][3], x23.y, b1w);
                    fma2(acc[2][3], x23.y, b2w); fma2(acc[3][3], x23.y, b3);
                    fma2(acc[0][4], x45.x, b0); fma2(acc[1][4], x45.x, b1w);
                    fma2(acc[2][4], x45.x, b2w); fma2(acc[3][4], x45.x, b3);
                    fma2(acc[0][5], x45.y, b0); fma2(acc[1][5], x45.y, b1w);
                    fma2(acc[2][5], x45.y, b2w); fma2(acc[3][5], x45.y, b3);
                    fma2(acc[0][6], x67.x, b0); fma2(acc[1][6], x67.x, b1w);
                    fma2(acc[2][6], x67.x, b2w); fma2(acc[3][6], x67.x, b3);
                    fma2(acc[0][7], x67.y, b0); fma2(acc[1][7], x67.y, b1w);
                    fma2(acc[2][7], x67.y, b2w); fma2(acc[3][7], x67.y, b3);
                }
            }
#pragma unroll
            for (int s = 0; s < 4; s++)
                wA[s] = __ldg((const float4*)(d0 + (size_t)(b2 * 4 + s) * NH));
            {
                const int hb = b1 * 4;
#pragma unroll
                for (int s = 0; s < 4; s++) {
                    ull b0 = pack2(wB[s].x, wB[s].x), b1w = pack2(wB[s].y, wB[s].y);
                    ull b2w = pack2(wB[s].z, wB[s].z), b3 = pack2(wB[s].w, wB[s].w);
                    const ulonglong2* xr = reinterpret_cast<const ulonglong2*>(&xs[hb + s][0]);
                    ulonglong2 x01 = xr[0], x23 = xr[1], x45 = xr[2], x67 = xr[3];
                    fma2(acc[0][0], x01.x, b0); fma2(acc[1][0], x01.x, b1w);
                    fma2(acc[2][0], x01.x, b2w); fma2(acc[3][0], x01.x, b3);
                    fma2(acc[0][1], x01.y, b0); fma2(acc[1][1], x01.y, b1w);
                    fma2(acc[2][1], x01.y, b2w); fma2(acc[3][1], x01.y, b3);
                    fma2(acc[0][2], x23.x, b0); fma2(acc[1][2], x23.x, b1w);
                    fma2(acc[2][2], x23.x, b2w); fma2(acc[3][2], x23.x, b3);
                    fma2(acc[0][3], x23.y, b0); fma2(acc[1][3], x23.y, b1w);
                    fma2(acc[2][3], x23.y, b2w); fma2(acc[3][3], x23.y, b3);
                    fma2(acc[0][4], x45.x, b0); fma2(acc[1][4], x45.x, b1w);
                    fma2(acc[2][4], x45.x, b2w); fma2(acc[3][4], x45.x, b3);
                    fma2(acc[0][5], x45.y, b0); fma2(acc[1][5], x45.y, b1w);
                    fma2(acc[2][5], x45.y, b2w); fma2(acc[3][5], x45.y, b3);
                    fma2(acc[0][6], x67.x, b0); fma2(acc[1][6], x67.x, b1w);
                    fma2(acc[2][6], x67.x, b2w); fma2(acc[3][6], x67.x, b3);
                    fma2(acc[0][7], x67.y, b0); fma2(acc[1][7], x67.y, b1w);
                    fma2(acc[2][7], x67.y, b2w); fma2(acc[3][7], x67.y, b3);
                }
            }
        }
    }

    float* pp = g_part + ((size_t)z * NE * NM + (size_t)e * NM) * NH + h0;
#pragma unroll
    for (int j = 0; j < 8; j++) {
        float2 r0 = unpack2(acc[0][j]), r1 = unpack2(acc[1][j]);
        float2 r2 = unpack2(acc[2][j]), r3 = unpack2(acc[3][j]);
        float4 v0 = make_float4(r0.x, r1.x, r2.x, r3.x);
        float4 v1 = make_float4(r0.y, r1.y, r2.y, r3.y);
        *reinterpret_cast<float4*>(pp + (size_t)(2 * j) * NH)     = v0;
        *reinterpret_cast<float4*>(pp + (size_t)(2 * j + 1) * NH) = v1;
    }
}

// ---------------------------------------------------------------------------
// Kernel 3: out = part[0] + part[1]
// ---------------------------------------------------------------------------
__global__ __launch_bounds__(256) void moe_reduce_kernel(float* __restrict__ out)
{
    const size_t i = (size_t)blockIdx.x * 256 + threadIdx.x;   // float4 index
    const size_t n4 = (size_t)NE * NM * NH / 4;
    if (i < n4) {
        const float4* p0 = reinterpret_cast<const float4*>(g_part);
        const float4* p1 = reinterpret_cast<const float4*>(g_part + (size_t)NE * NM * NH);
        float4 a = p0[i], b = p1[i];
        float4 r = make_float4(a.x + b.x, a.y + b.y, a.z + b.z, a.w + b.w);
        reinterpret_cast<float4*>(out)[i] = r;
    }
}

extern "C" void kernel_launch(void* const* d_in, const int* in_sizes, int n_in,
                              void* d_out, int out_size)
{
    const float* x    = (const float*)d_in[0];  // [T=1024, H=2048]
    const float* gate = (const float*)d_in[1];  // [E, H, F]
    const float* up   = (const float*)d_in[2];  // [E, H, F]
    const float* down = (const float*)d_in[3];  // [E, F, H]
    float* out = (float*)d_out;                 // [T, H] fp32

    dim3 g1(NF / 128, NE);        // 11 x 64 = 704 CTAs, 64 thr
    moe_gateup_kernel<<<g1, 64>>>(x, gate, up);

    dim3 g2(NH / 256, NE, 2);     // 8 x 64 x 2 = 1024 CTAs, 64 thr
    moe_down_kernel<<<g2, 64>>>(down);

    const int n4 = NE * NM * NH / 4;              // 524288
    moe_reduce_kernel<<<(n4 + 255) / 256, 256>>>(out);
}